// round 16
// baseline (speedup 1.0000x reference)
#include <cuda_runtime.h>
#include <cstdint>

#define BB 256
#define SS 128
#define DD 768
#define KK 1536           // 2*DD
#define NSPLIT 3          // split-K factor for kB
#define MN (BB * DD)      // 196608

#define KA_TILE 8
#define KA_TILEF (KA_TILE * DD)        // 6144 floats per tile buffer
#define T_ML  (2 * KA_TILEF)           // 12288
#define T_SC  (T_ML + DD)              // 13056
#define T_SCW (T_SC + 8)               // 13064
#define T_PRE (T_SCW + 8)              // 13072 (2x8)
#define T_FAC (T_PRE + 16)             // 13088
#define KA_SMEM_BYTES ((T_FAC + 16) * 4)   // 52416 B

// scratch (device globals; no allocations allowed)
__device__ float g_feats[BB * KK];          // tf32-rounded [att | mask_logits]
__device__ float g_part[NSPLIT * MN];       // split-K partials of feats @ W^T
__device__ float g_patt[2 * BB * DD];       // split-seq att partials (unnormalized)
__device__ float g_ml2[BB * 4];             // per-half (m, l)
__device__ int   g_cnt[BB];                 // arrival counters (zero-init, reset after merge)

__constant__ int c_ids[21] = {
    2307, 2204, 3835, 2157, 6581, 2986, 5151, 3893,
    7929, 24791, 8699, 4257, 16021, 6623,
    6659, 2919, 11771, 3532, 11325, 4997, 13135
};

__device__ __forceinline__ float warp_sum(float v) {
    #pragma unroll
    for (int o = 16; o; o >>= 1) v += __shfl_xor_sync(0xffffffffu, v, o);
    return v;
}

__device__ __forceinline__ float tf32r(float x) {
    float r;
    asm volatile("cvt.rna.tf32.f32 %0, %1;" : "=f"(r) : "f"(x));
    return r;
}

#define CP_ASYNC16(dst, src) \
    asm volatile("cp.async.cg.shared.global [%0], [%1], 16;" :: "r"(dst), "l"(src))

__device__ __forceinline__ void mma_tf32(float* c, const uint32_t* a, const uint32_t* b) {
    asm volatile(
        "mma.sync.aligned.m16n8k8.row.col.f32.tf32.tf32.f32 "
        "{%0,%1,%2,%3}, {%4,%5,%6,%7}, {%8,%9}, {%0,%1,%2,%3};"
        : "+f"(c[0]), "+f"(c[1]), "+f"(c[2]), "+f"(c[3])
        : "r"(a[0]), "r"(a[1]), "r"(a[2]), "r"(a[3]), "r"(b[0]), "r"(b[1]));
}

// ---------------------------------------------------------------------------
// kA: TWO CTAs per batch row (split sequence halves), flash-style.
//   CTA (b, h): rows [3 + h*L0, ...) where L0 = (L+1)/2.  8-row smem tiles,
//   double-buffered cp.async; per-tile score -> online softmax -> att.
//   Each CTA writes unnormalized att partial + (m, l); the SECOND CTA to
//   finish (atomic counter) merges both partials (reading the partner's data
//   with ld.global.cg — L2 scope, since L1 is not coherent across SMs) and
//   writes feats.  h==0 additionally does pooler head + mask-logits write.
// ---------------------------------------------------------------------------
__global__ __launch_bounds__(256) void kA(
    const float* __restrict__ bert, const int* __restrict__ len,
    const float* __restrict__ sw, const float* __restrict__ sb,
    float* __restrict__ out)
{
    extern __shared__ float sm[];
    float* tiles = sm;
    float* ml_s  = sm + T_ML;
    float* sc_t  = sm + T_SC;
    float* scw   = sm + T_SCW;
    float* pre   = sm + T_PRE;   // [2][8]
    float* sfac  = sm + T_FAC;   // [0]=rescale, [1]=m_own, [2]=l_own
    __shared__ int sflag;

    int b = blockIdx.x, h = blockIdx.y, tid = threadIdx.x;
    int wid = tid >> 5, lane = tid & 31;

    const float* base = bert + (size_t)b * SS * DD;
    int L = len[b];
    int L0 = (L + 1) >> 1;
    int Lh = h ? (L - L0) : L0;
    int s0 = 3 + h * L0;
    int ntiles = (Lh + KA_TILE - 1) / KA_TILE;

    uint32_t smaddr = (uint32_t)__cvta_generic_to_shared(sm);

    auto issue = [&](int t) {
        const float* src = base + (size_t)(s0 + t * KA_TILE) * DD;
        uint32_t dstb = smaddr + ((t & 1) * KA_TILEF) * 4;
        #pragma unroll
        for (int k = 0; k < 6; k++) {
            int j = tid + k * 256;
            CP_ASYNC16(dstb + j * 16, src + j * 4);
        }
    };

    issue(0);
    asm volatile("cp.async.commit_group;");

    // mask logits row -> smem (both halves need it for scores)
    const float* mr = base + (size_t)(3 + L) * DD;
    float* feats = g_feats + (size_t)b * KK;
    #pragma unroll
    for (int d = tid; d < DD; d += 256) {
        float v = mr[d];
        ml_s[d] = v;
        if (h == 0) feats[DD + d] = tf32r(v);
    }

    // pooler head (row 0) — h==0 only
    if (h == 0) {
        float p0 = base[tid], p1 = base[tid + 256], p2 = base[tid + 512];
        float c0 = fmaf(p0, sw[tid], fmaf(p1, sw[tid + 256], p2 * sw[tid + 512]));
        float c1 = fmaf(p0, sw[DD + tid], fmaf(p1, sw[DD + tid + 256], p2 * sw[DD + tid + 512]));
        c0 = warp_sum(c0);
        c1 = warp_sum(c1);
        if (lane == 0) { pre[2 * wid] = c0; pre[2 * wid + 1] = c1; }
    }

    float rm = -1e30f, rl = 0.f;          // live in warp0 lanes
    float a0 = 0.f, a1 = 0.f, a2 = 0.f;

    for (int t = 0; t < ntiles; t++) {
        if (t + 1 < ntiles) {
            issue(t + 1);
            asm volatile("cp.async.commit_group;");
            asm volatile("cp.async.wait_group 1;");
        } else {
            asm volatile("cp.async.wait_group 0;");
        }
        __syncthreads();   // tile t visible; publishes ml_s/pre on t==0

        if (t == 0 && h == 0 && tid == 0) {
            float a = 0.f, c = 0.f;
            #pragma unroll
            for (int i = 0; i < 8; i++) { a += pre[2 * i]; c += pre[2 * i + 1]; }
            out[b * 2 + 0] = a + sb[0];
            out[b * 2 + 1] = c + sb[1];
        }

        const float* tb = tiles + (t & 1) * KA_TILEF;

        // scores: warp wid handles row wid (8 warps, 8 rows)
        {
            int sl = t * KA_TILE + wid;
            const float* r = tb + wid * DD;
            float acc = 0.f;
            #pragma unroll 6
            for (int q = lane; q < DD; q += 32)
                acc = fmaf(r[q], ml_s[q], acc);
            acc = warp_sum(acc);
            if (lane == 0) sc_t[wid] = (sl < Lh) ? acc : -1e30f;
        }
        __syncthreads();

        // warp 0: online-softmax weights for this tile
        if (tid < 32) {
            float v = (lane < KA_TILE) ? sc_t[lane] : -1e30f;
            float tm = v;
            #pragma unroll
            for (int o = 16; o; o >>= 1) tm = fmaxf(tm, __shfl_xor_sync(0xffffffffu, tm, o));
            float nm = fmaxf(rm, tm);
            float f = __expf(rm - nm);
            float w = (lane < KA_TILE && v > -1e29f) ? __expf(v - nm) : 0.f;
            float ws = warp_sum(w);
            rl = rl * f + ws;
            rm = nm;
            if (lane < KA_TILE) scw[lane] = w;
            if (lane == 0) sfac[0] = f;
        }
        __syncthreads();

        float f = sfac[0];
        a0 *= f; a1 *= f; a2 *= f;
        #pragma unroll
        for (int i = 0; i < KA_TILE; i++) {
            float w = scw[i];
            const float* r = tb + i * DD;
            a0 = fmaf(w, r[tid], a0);
            a1 = fmaf(w, r[tid + 256], a1);
            a2 = fmaf(w, r[tid + 512], a2);
        }
        __syncthreads();   // buffer safe for reuse by next issue
    }

    if (tid < 32 && lane == 0) { sfac[1] = rm; sfac[2] = rl; }
    __syncthreads();
    float m_own = sfac[1], l_own = sfac[2];

    // publish this half's partial
    float* Pa = g_patt + ((size_t)h * BB + b) * DD;
    Pa[tid]       = a0;
    Pa[tid + 256] = a1;
    Pa[tid + 512] = a2;
    if (tid == 0) {
        g_ml2[b * 4 + h * 2]     = m_own;
        g_ml2[b * 4 + h * 2 + 1] = l_own;
    }
    __threadfence();
    if (tid == 0) sflag = atomicAdd(&g_cnt[b], 1);
    __syncthreads();
    if (sflag != 1) return;          // first finisher exits; second merges
    __threadfence();

    int ph = 1 - h;
    float m_p = __ldcg(&g_ml2[b * 4 + ph * 2]);
    float l_p = __ldcg(&g_ml2[b * 4 + ph * 2 + 1]);
    float ms = fmaxf(m_own, m_p);
    float e0 = __expf(m_own - ms), e1 = __expf(m_p - ms);
    float inv = 1.f / (l_own * e0 + l_p * e1);
    const float* Pp = g_patt + ((size_t)ph * BB + b) * DD;
    feats[tid]       = tf32r((a0 * e0 + __ldcg(Pp + tid)       * e1) * inv);
    feats[tid + 256] = tf32r((a1 * e0 + __ldcg(Pp + tid + 256) * e1) * inv);
    feats[tid + 512] = tf32r((a2 * e0 + __ldcg(Pp + tid + 512) * e1) * inv);
    if (tid == 0) g_cnt[b] = 0;      // reset for next replay
}

// ---------------------------------------------------------------------------
// kB: TF32 tensor-core GEMM, split-K=3, STATIC smem (36 KB).
//   C[256,768] partials = feats[256,1536] @ dense_w[768,1536]^T
//   dense_w loaded RAW fp32 via cp.async; B fragments rounded to tf32 with
//   cvt.rna after LDS.  CTA tile 64x64, BK=32, 16 stages, cp.async x2 buf.
//   grid (12, 4, 3) = 144 CTAs.  smem rows padded to 36 floats.
// ---------------------------------------------------------------------------
#define KB_BUF (128 * 36)

__global__ __launch_bounds__(256) void kB(const float* __restrict__ W)
{
    __shared__ float sm[2 * KB_BUF];

    int tid = threadIdx.x;
    int wid = tid >> 5, lane = tid & 31;
    int warp_m = wid >> 2, warp_n = wid & 3;
    int g = lane >> 2, t = lane & 3;

    int mBase = blockIdx.y * 64;
    int nBase = blockIdx.x * 64;
    int kBase = blockIdx.z * (KK / NSPLIT);

    uint32_t smaddr = (uint32_t)__cvta_generic_to_shared(sm);

    float acc[2][2][4] = {};

    auto load_stage = [&](int buf, int s) {
        uint32_t sb = smaddr + buf * (KB_BUF * 4);
        int kb = kBase + s * 32;
        #pragma unroll
        for (int i = 0; i < 2; i++) {
            int c = tid + i * 256;
            int row = c >> 3, q = c & 7;
            uint32_t dst = sb + (row * 36 + q * 4) * 4;
            const float* src = g_feats + (size_t)(mBase + row) * KK + kb + q * 4;
            CP_ASYNC16(dst, src);
        }
        #pragma unroll
        for (int i = 0; i < 2; i++) {
            int c = tid + i * 256;
            int row = c >> 3, q = c & 7;
            uint32_t dst = sb + ((64 + row) * 36 + q * 4) * 4;
            const float* src = W + (size_t)(nBase + row) * KK + kb + q * 4;
            CP_ASYNC16(dst, src);
        }
    };

    load_stage(0, 0);
    asm volatile("cp.async.commit_group;");

    const int NSTAGE = 16;
    for (int s = 0; s < NSTAGE; s++) {
        if (s + 1 < NSTAGE) load_stage((s + 1) & 1, s + 1);
        asm volatile("cp.async.commit_group;");
        if (s + 1 < NSTAGE) asm volatile("cp.async.wait_group 1;");
        else                asm volatile("cp.async.wait_group 0;");
        __syncthreads();

        const uint32_t* As = (const uint32_t*)(sm + (s & 1) * KB_BUF);
        const uint32_t* Bs = As + 64 * 36;
        int am = (warp_m * 32 + g) * 36;
        int bn = (warp_n * 16 + g) * 36;

        #pragma unroll
        for (int ks = 0; ks < 4; ks++) {
            int kk = ks * 8;
            uint32_t a[2][4], bfr[2][2];
            #pragma unroll
            for (int mf = 0; mf < 2; mf++) {
                int r0 = am + mf * 576 + kk + t;
                a[mf][0] = As[r0];
                a[mf][1] = As[r0 + 288];
                a[mf][2] = As[r0 + 4];
                a[mf][3] = As[r0 + 288 + 4];
            }
            #pragma unroll
            for (int nf = 0; nf < 2; nf++) {
                int r0 = bn + nf * 288 + kk + t;
                bfr[nf][0] = __float_as_uint(tf32r(__uint_as_float(Bs[r0])));
                bfr[nf][1] = __float_as_uint(tf32r(__uint_as_float(Bs[r0 + 4])));
            }
            #pragma unroll
            for (int mf = 0; mf < 2; mf++)
                #pragma unroll
                for (int nf = 0; nf < 2; nf++)
                    mma_tf32(acc[mf][nf], a[mf], bfr[nf]);
        }
        __syncthreads();
    }

    float* P = g_part + (size_t)blockIdx.z * MN;
    #pragma unroll
    for (int mf = 0; mf < 2; mf++) {
        int m = mBase + warp_m * 32 + mf * 16 + g;
        #pragma unroll
        for (int nf = 0; nf < 2; nf++) {
            int n = nBase + warp_n * 16 + nf * 8 + t * 2;
            float2 v0 = make_float2(acc[mf][nf][0], acc[mf][nf][1]);
            float2 v1 = make_float2(acc[mf][nf][2], acc[mf][nf][3]);
            *(float2*)(P + (size_t)m * DD + n)       = v0;
            *(float2*)(P + (size_t)(m + 8) * DD + n) = v1;
        }
    }
}

// ---------------------------------------------------------------------------
// kC: 512 threads. Decoder rows PREFETCHED into registers (independent of h)
// so the dec_w load latency overlaps the split-K partial-reduce latency.
// ---------------------------------------------------------------------------
__global__ __launch_bounds__(512) void kC(
    const float* __restrict__ db, const float* __restrict__ decw,
    const float* __restrict__ decb, const float* __restrict__ w0,
    const float* __restrict__ w1, const float* __restrict__ w2,
    float* __restrict__ out)
{
    int b = blockIdx.x, tid = threadIdx.x;
    int wid = tid >> 5, lane = tid & 31;

    __shared__ __align__(16) float h[DD];
    __shared__ float pr[24];

    int nrows = (wid < 5) ? 2 : 1;
    float4 wreg[2][6];
    #pragma unroll
    for (int rr = 0; rr < 2; rr++) {
        if (rr < nrows) {
            int id = c_ids[wid + rr * 16];
            const float4* r4 = (const float4*)(decw + (size_t)id * DD);
            #pragma unroll
            for (int q = 0; q < 6; q++)
                wreg[rr][q] = r4[lane + 32 * q];
        }
    }

    {
        float s = db[tid];
        #pragma unroll
        for (int kz = 0; kz < NSPLIT; kz++)
            s += g_part[(size_t)kz * MN + (size_t)b * DD + tid];
        h[tid] = tanhf(s);
        if (tid < 256) {
            int d = tid + 512;
            float s2 = db[d];
            #pragma unroll
            for (int kz = 0; kz < NSPLIT; kz++)
                s2 += g_part[(size_t)kz * MN + (size_t)b * DD + d];
            h[d] = tanhf(s2);
        }
    }
    __syncthreads();

    const float4* h4 = (const float4*)h;
    #pragma unroll
    for (int rr = 0; rr < 2; rr++) {
        if (rr < nrows) {
            int j = wid + rr * 16;
            float acc = 0.f;
            #pragma unroll
            for (int q = 0; q < 6; q++) {
                float4 w = wreg[rr][q];
                float4 hv = h4[lane + 32 * q];
                acc = fmaf(w.x, hv.x, fmaf(w.y, hv.y, fmaf(w.z, hv.z, fmaf(w.w, hv.w, acc))));
            }
            acc = warp_sum(acc);
            if (lane == 0) pr[j] = tanhf(acc + decb[c_ids[j]]);
        }
    }
    __syncthreads();

    if (tid < 6) {
        int grp = tid % 3, jr = tid / 3;
        const float* w;
        int off, nk;
        if (grp == 0)      { w = w0; off = 0;  nk = 8; }
        else if (grp == 1) { w = w1; off = 8;  nk = 6; }
        else               { w = w2; off = 14; nk = 7; }
        float acc = 0.f;
        for (int k = 0; k < nk; k++) acc = fmaf(pr[off + k], w[jr * nk + k], acc);
        out[2 * BB + b * 6 + jr * 3 + grp] = acc;
    }
}

extern "C" void kernel_launch(void* const* d_in, const int* in_sizes, int n_in,
                              void* d_out, int out_size)
{
    const float* bert    = (const float*)d_in[0];
    const int*   len     = (const int*)  d_in[2];
    const float* senti_w = (const float*)d_in[3];
    const float* senti_b = (const float*)d_in[4];
    const float* dense_w = (const float*)d_in[5];
    const float* dense_b = (const float*)d_in[6];
    const float* dec_w   = (const float*)d_in[7];
    const float* dec_b   = (const float*)d_in[8];
    const float* w0      = (const float*)d_in[9];
    const float* w1      = (const float*)d_in[10];
    const float* w2      = (const float*)d_in[11];
    float* out = (float*)d_out;

    cudaFuncSetAttribute(kA, cudaFuncAttributeMaxDynamicSharedMemorySize,
                         KA_SMEM_BYTES);

    kA<<<dim3(BB, 2), 256, KA_SMEM_BYTES>>>(bert, len, senti_w, senti_b, out);
    kB<<<dim3(DD / 64, BB / 64, NSPLIT), 256>>>(dense_w);
    kC<<<BB, 512>>>(dense_b, dec_w, dec_b, w0, w1, w2, out);
}